// round 7
// baseline (speedup 1.0000x reference)
#include <cuda_runtime.h>

// Problem constants
#define NMAX   50000
#define EMAX   800000
#define IN_DIM 128
#define H1DIM  128   // HEADS*HID
#define NHEADS 4
#define HID    32
#define OUTD   64
#define SLOPE  0.2f

// ---------------- scratch (static __device__ globals; no allocation) ----------
__device__ int   g_is64;
__device__ int   g_deg[NMAX];
__device__ int   g_off[NMAX];
__device__ int   g_cur[NMAX];
__device__ int   g_csr[EMAX];
__device__ float g_h1  [NMAX * H1DIM];
__device__ float g_als1[NMAX * NHEADS];
__device__ float g_ald1[NMAX * NHEADS];
__device__ float g_out1[NMAX * H1DIM];
__device__ float g_h2  [NMAX * OUTD];
__device__ float g_als2[NMAX];
__device__ float g_ald2[NMAX];

// ---------------- edge dtype detect + access --------------------------------
// If edge_index is int64 (little endian, values < 2^31), every odd 32-bit word
// is zero. If int32, odd words are random edge values in [0, N) — the chance
// all 32 probes are zero is ~0.
__global__ void k_detect(const unsigned int* __restrict__ p) {
    unsigned v = p[threadIdx.x * 2 + 1];
    unsigned all0 = __all_sync(0xffffffffu, v == 0u);
    if (threadIdx.x == 0) g_is64 = (int)all0;
}

__device__ __forceinline__ int edge_at(const void* p, long long i) {
    if (g_is64) return (int)((const long long*)p)[i];
    return ((const int*)p)[i];
}

// ---------------- CSR build --------------------------------------------------
__global__ void k_zero(int n) {
    int i = blockIdx.x * blockDim.x + threadIdx.x;
    if (i < n) g_deg[i] = 0;
}

__global__ void k_count(const void* __restrict__ ei, int e) {
    int i = blockIdx.x * blockDim.x + threadIdx.x;
    if (i < e) {
        int d = edge_at(ei, (long long)e + i);   // dst row
        atomicAdd(&g_deg[d], 1);
    }
}

// single-block exclusive scan over n (n <= 50176): 1024 threads, chunked
__global__ void k_scan(int n) {
    __shared__ int sm[1024];
    int t  = threadIdx.x;
    int ch = (n + 1023) >> 10;
    int lo = t * ch;
    int hi = min(lo + ch, n);
    int s = 0;
    for (int i = lo; i < hi; i++) s += g_deg[i];
    sm[t] = s;
    __syncthreads();
    for (int d = 1; d < 1024; d <<= 1) {
        int v = (t >= d) ? sm[t - d] : 0;
        __syncthreads();
        sm[t] += v;
        __syncthreads();
    }
    int run = (t > 0) ? sm[t - 1] : 0;
    for (int i = lo; i < hi; i++) {
        g_off[i] = run;
        g_cur[i] = run;
        run += g_deg[i];
    }
}

__global__ void k_scatter(const void* __restrict__ ei, int e) {
    int i = blockIdx.x * blockDim.x + threadIdx.x;
    if (i < e) {
        int s = edge_at(ei, i);
        int d = edge_at(ei, (long long)e + i);
        int pos = atomicAdd(&g_cur[d], 1);
        g_csr[pos] = s;
    }
}

// ---------------- fp32 tiled GEMM, K = 128 fixed -----------------------------
// C[M,BN] = A[M,128] @ B[128,BN].  256 threads, BM=64, BK=32.
template <int BN>
__device__ __forceinline__ void gemm128(const float* __restrict__ A,
                                        const float* __restrict__ B,
                                        float* __restrict__ C, int M) {
    constexpr int K = 128, BM = 64, BK = 32;
    constexpr int TX = BN / 4;       // 32 (BN=128) or 16 (BN=64)
    constexpr int TY = 256 / TX;     // 8 or 16
    constexpr int TM = BM / TY;      // 8 or 4
    __shared__ float As[BM][BK];
    __shared__ float Bs[BK][BN];
    int tid = threadIdx.x;
    int tx = tid % TX, ty = tid / TX;
    int row0 = blockIdx.x * BM;

    float acc[TM][4];
#pragma unroll
    for (int i = 0; i < TM; i++) { acc[i][0] = acc[i][1] = acc[i][2] = acc[i][3] = 0.f; }

    for (int kt = 0; kt < K; kt += BK) {
#pragma unroll
        for (int j = 0; j < (BM * BK) / 256; j++) {
            int idx = tid + j * 256;
            int r = idx >> 5;        // /BK (BK=32)
            int kk = idx & 31;
            int grow = row0 + r;
            As[r][kk] = (grow < M) ? A[(long long)grow * K + kt + kk] : 0.f;
        }
#pragma unroll
        for (int j = 0; j < (BK * BN) / 256; j++) {
            int idx = tid + j * 256;
            int kk = idx / BN;
            int nn = idx % BN;
            Bs[kk][nn] = B[(kt + kk) * BN + nn];
        }
        __syncthreads();
#pragma unroll
        for (int kk = 0; kk < BK; kk++) {
            float4 b4 = *(const float4*)&Bs[kk][tx * 4];
#pragma unroll
            for (int i = 0; i < TM; i++) {
                float a = As[ty + i * TY][kk];
                acc[i][0] = fmaf(a, b4.x, acc[i][0]);
                acc[i][1] = fmaf(a, b4.y, acc[i][1]);
                acc[i][2] = fmaf(a, b4.z, acc[i][2]);
                acc[i][3] = fmaf(a, b4.w, acc[i][3]);
            }
        }
        __syncthreads();
    }
#pragma unroll
    for (int i = 0; i < TM; i++) {
        int r = row0 + ty + i * TY;
        if (r < M) {
            float4 o = make_float4(acc[i][0], acc[i][1], acc[i][2], acc[i][3]);
            *(float4*)&C[(long long)r * BN + tx * 4] = o;
        }
    }
}

__global__ void k_gemm1(const float* __restrict__ x, const float* __restrict__ W1, int M) {
    gemm128<H1DIM>(x, W1, g_h1, M);
}
__global__ void k_gemm2(const float* __restrict__ W2, int M) {
    gemm128<OUTD>(g_out1, W2, g_h2, M);
}

// ---------------- attention coefficients (warp per node) ---------------------
// als[n,h] = sum_c h[n, h*C + c] * a_s[h*C + c]   (a flattened to K floats)
template <int K, int H>
__device__ __forceinline__ void alpha_body(const float* __restrict__ h,
                                           const float* __restrict__ a_s,
                                           const float* __restrict__ a_d,
                                           float* __restrict__ als,
                                           float* __restrict__ ald, int n) {
    int w = (blockIdx.x * blockDim.x + threadIdx.x) >> 5;
    int lane = threadIdx.x & 31;
    if (w >= n) return;
    constexpr int L = K / 4;        // active lanes
    constexpr int GRP = L / H;      // lanes per head
    float ps = 0.f, pd = 0.f;
    if (lane < L) {
        float4 v  = *(const float4*)&h[(long long)w * K + lane * 4];
        float4 s4 = *(const float4*)&a_s[lane * 4];
        float4 d4 = *(const float4*)&a_d[lane * 4];
        ps = v.x * s4.x + v.y * s4.y + v.z * s4.z + v.w * s4.w;
        pd = v.x * d4.x + v.y * d4.y + v.z * d4.z + v.w * d4.w;
    }
#pragma unroll
    for (int o = GRP / 2; o > 0; o >>= 1) {
        ps += __shfl_down_sync(0xffffffffu, ps, o);
        pd += __shfl_down_sync(0xffffffffu, pd, o);
    }
    if (lane < L && (lane % GRP) == 0) {
        int head = lane / GRP;
        als[w * H + head] = ps;
        ald[w * H + head] = pd;
    }
}

__global__ void k_alpha1(const float* __restrict__ a_s, const float* __restrict__ a_d, int n) {
    alpha_body<H1DIM, NHEADS>(g_h1, a_s, a_d, g_als1, g_ald1, n);
}
__global__ void k_alpha2(const float* __restrict__ a_s, const float* __restrict__ a_d, int n) {
    alpha_body<OUTD, 1>(g_h2, a_s, a_d, g_als2, g_ald2, n);
}

__device__ __forceinline__ float lrelu(float e) { return e > 0.f ? e : SLOPE * e; }

// ---------------- layer 1 aggregation: warp per dst, lane = channel ----------
// out1[i, h*32+lane] = relu( (sum_src w*h1[src]) / (sum w) + b1 ), w = exp(lrelu(as[s]+ad[i]))
__global__ void k_agg1(const float* __restrict__ b1, int n) {
    int w = (blockIdx.x * blockDim.x + threadIdx.x) >> 5;
    int lane = threadIdx.x & 31;
    if (w >= n) return;

    float4 ad4 = *(const float4*)&g_ald1[w * 4];
    float adh[4] = {ad4.x, ad4.y, ad4.z, ad4.w};
    float4 as4 = *(const float4*)&g_als1[w * 4];
    float ash[4] = {as4.x, as4.y, as4.z, as4.w};

    float acc[4], z[4];
#pragma unroll
    for (int h = 0; h < 4; h++) {
        float wt = __expf(lrelu(ash[h] + adh[h]));   // self loop
        z[h] = wt;
        acc[h] = wt * g_h1[(long long)w * 128 + h * 32 + lane];
    }

    int p = g_off[w];
    int end = p + g_deg[w];
    int s = (p < end) ? g_csr[p] : 0;
    for (; p < end; p++) {
        int sc = s;
        if (p + 1 < end) s = g_csr[p + 1];           // prefetch next src id
        float4 a2 = *(const float4*)&g_als1[sc * 4];
        float a2h[4] = {a2.x, a2.y, a2.z, a2.w};
#pragma unroll
        for (int h = 0; h < 4; h++) {
            float wt = __expf(lrelu(a2h[h] + adh[h]));
            z[h] += wt;
            acc[h] = fmaf(wt, g_h1[(long long)sc * 128 + h * 32 + lane], acc[h]);
        }
    }
#pragma unroll
    for (int h = 0; h < 4; h++) {
        float v = acc[h] / (z[h] + 1e-16f) + b1[h * 32 + lane];
        g_out1[(long long)w * 128 + h * 32 + lane] = v > 0.f ? v : 0.f;
    }
}

// ---------------- layer 2 aggregation: warp per dst, lane covers c, c+32 -----
__global__ void k_agg2(const float* __restrict__ b2, float* __restrict__ out, int n) {
    int w = (blockIdx.x * blockDim.x + threadIdx.x) >> 5;
    int lane = threadIdx.x & 31;
    if (w >= n) return;

    float ad = g_ald2[w];
    float wt = __expf(lrelu(g_als2[w] + ad));        // self loop
    float z = wt;
    float acc0 = wt * g_h2[(long long)w * 64 + lane];
    float acc1 = wt * g_h2[(long long)w * 64 + 32 + lane];

    int p = g_off[w];
    int end = p + g_deg[w];
    int s = (p < end) ? g_csr[p] : 0;
    for (; p < end; p++) {
        int sc = s;
        if (p + 1 < end) s = g_csr[p + 1];
        float wt2 = __expf(lrelu(g_als2[sc] + ad));
        z += wt2;
        acc0 = fmaf(wt2, g_h2[(long long)sc * 64 + lane], acc0);
        acc1 = fmaf(wt2, g_h2[(long long)sc * 64 + 32 + lane], acc1);
    }
    float inv = 1.f / (z + 1e-16f);
    out[(long long)w * 64 + lane]      = acc0 * inv + b2[lane];
    out[(long long)w * 64 + 32 + lane] = acc1 * inv + b2[32 + lane];
}

// ---------------- launch -----------------------------------------------------
extern "C" void kernel_launch(void* const* d_in, const int* in_sizes, int n_in,
                              void* d_out, int out_size) {
    const float* x   = (const float*)d_in[0];
    const void*  ei  = d_in[1];                    // edge_index [2,E], int64 or int32
    const float* W1  = (const float*)d_in[3];
    const float* as1 = (const float*)d_in[4];
    const float* ad1 = (const float*)d_in[5];
    const float* b1  = (const float*)d_in[6];
    const float* W2  = (const float*)d_in[7];
    const float* as2 = (const float*)d_in[8];
    const float* ad2 = (const float*)d_in[9];
    const float* b2  = (const float*)d_in[10];
    float* out = (float*)d_out;

    int n = in_sizes[0] / IN_DIM;                  // 50000
    int e = in_sizes[1] / 2;                       // 800000

    // edge dtype detection (probe odd 32-bit words)
    k_detect<<<1, 32>>>((const unsigned int*)ei);

    // CSR build over dst
    k_zero<<<(n + 255) / 256, 256>>>(n);
    k_count<<<(e + 255) / 256, 256>>>(ei, e);
    k_scan<<<1, 1024>>>(n);
    k_scatter<<<(e + 255) / 256, 256>>>(ei, e);

    // layer 1
    k_gemm1<<<(n + 63) / 64, 256>>>(x, W1, n);
    k_alpha1<<<(n * 32 + 255) / 256, 256>>>(as1, ad1, n);
    k_agg1<<<(n + 7) / 8, 256>>>(b1, n);

    // layer 2
    k_gemm2<<<(n + 63) / 64, 256>>>(W2, n);
    k_alpha2<<<(n * 32 + 255) / 256, 256>>>(as2, ad2, n);
    k_agg2<<<(n + 7) / 8, 256>>>(b2, out, n);
}

// round 10
// speedup vs baseline: 1.3243x; 1.3243x over previous
#include <cuda_runtime.h>

// Problem constants
#define NMAX   50000
#define EMAX   800000
#define IN_DIM 128
#define H1DIM  128   // HEADS*HID
#define NHEADS 4
#define HID    32
#define OUTD   64
#define SLOPE  0.2f

#define SCAN_CHUNK 1024
#define MAX_PARTS  64          // ceil(50000/1024)=49 < 64

// ---------------- scratch (static __device__ globals; no allocation) ----------
__device__ int   g_is64;
__device__ int   g_deg[NMAX];
__device__ int   g_off[NMAX];
__device__ int   g_cur[NMAX];
__device__ int   g_part[MAX_PARTS];
__device__ int   g_csr[EMAX];
__device__ float g_h1  [NMAX * H1DIM];
__device__ float g_als1[NMAX * NHEADS];
__device__ float g_ald1[NMAX * NHEADS];
__device__ float g_out1[NMAX * H1DIM];
__device__ float g_h2  [NMAX * OUTD];
__device__ float g_als2[NMAX];
__device__ float g_ald2[NMAX];

// ---------------- edge dtype detect + access --------------------------------
// If edge_index is int64 (little endian, values < 2^31), every odd 32-bit word
// is zero. If int32, odd words are random edge values in [0, N).
__global__ void k_detect(const unsigned int* __restrict__ p) {
    unsigned v = p[threadIdx.x * 2 + 1];
    unsigned all0 = __all_sync(0xffffffffu, v == 0u);
    if (threadIdx.x == 0) g_is64 = (int)all0;
}

__device__ __forceinline__ int edge_at(const void* p, long long i) {
    if (g_is64) return (int)((const long long*)p)[i];
    return ((const int*)p)[i];
}

// ---------------- CSR build --------------------------------------------------
__global__ void k_zero(int n) {
    int i = blockIdx.x * blockDim.x + threadIdx.x;
    if (i < n) g_deg[i] = 0;
}

__global__ void k_count(const void* __restrict__ ei, int e) {
    int i = blockIdx.x * blockDim.x + threadIdx.x;
    if (i < e) {
        int d = edge_at(ei, (long long)e + i);   // dst row
        atomicAdd(&g_deg[d], 1);
    }
}

// ---- phase 1: per-chunk (1024 elems) sums, grid = nb, block = 256 ----------
__global__ void k_scan_partial(int n) {
    __shared__ int sm[8];
    int b = blockIdx.x, t = threadIdx.x;
    int base = b * SCAN_CHUNK + t * 4;
    int s = 0;
#pragma unroll
    for (int j = 0; j < 4; j++) {
        int i = base + j;
        if (i < n) s += g_deg[i];
    }
#pragma unroll
    for (int o = 16; o > 0; o >>= 1) s += __shfl_down_sync(0xffffffffu, s, o);
    if ((t & 31) == 0) sm[t >> 5] = s;
    __syncthreads();
    if (t < 8) {
        int v = sm[t];
#pragma unroll
        for (int o = 4; o > 0; o >>= 1) v += __shfl_down_sync(0xffu, v, o);
        if (t == 0) g_part[b] = v;
    }
}

// ---- phase 2: exclusive scan of chunk sums (single tiny block) -------------
__global__ void k_scan_part(int nb) {
    __shared__ int sm[MAX_PARTS];
    int t = threadIdx.x;
    int v = (t < nb) ? g_part[t] : 0;
    sm[t] = v;
    __syncthreads();
#pragma unroll
    for (int d = 1; d < MAX_PARTS; d <<= 1) {
        int x = (t >= d) ? sm[t - d] : 0;
        __syncthreads();
        sm[t] += x;
        __syncthreads();
    }
    if (t < nb) g_part[t] = sm[t] - v;     // exclusive
}

// ---- phase 3: re-scan chunk with offset, write g_off / g_cur ---------------
__global__ void k_scan_final(int n) {
    __shared__ int sm[256];
    int b = blockIdx.x, t = threadIdx.x;
    int base = b * SCAN_CHUNK + t * 4;
    int v[4];
    int s = 0;
#pragma unroll
    for (int j = 0; j < 4; j++) {
        int i = base + j;
        v[j] = (i < n) ? g_deg[i] : 0;
        s += v[j];
    }
    sm[t] = s;
    __syncthreads();
#pragma unroll
    for (int d = 1; d < 256; d <<= 1) {
        int x = (t >= d) ? sm[t - d] : 0;
        __syncthreads();
        sm[t] += x;
        __syncthreads();
    }
    int run = g_part[b] + ((t > 0) ? sm[t - 1] : 0);
#pragma unroll
    for (int j = 0; j < 4; j++) {
        int i = base + j;
        if (i < n) {
            g_off[i] = run;
            g_cur[i] = run;
            run += v[j];
        }
    }
}

__global__ void k_scatter(const void* __restrict__ ei, int e) {
    int i = blockIdx.x * blockDim.x + threadIdx.x;
    if (i < e) {
        int s = edge_at(ei, i);
        int d = edge_at(ei, (long long)e + i);
        int pos = atomicAdd(&g_cur[d], 1);
        g_csr[pos] = s;
    }
}

// ---------------- fp32 tiled GEMM, K = 128 fixed -----------------------------
// C[M,BN] = A[M,128] @ B[128,BN].  256 threads, BM=64, BK=32.
template <int BN>
__device__ __forceinline__ void gemm128(const float* __restrict__ A,
                                        const float* __restrict__ B,
                                        float* __restrict__ C, int M) {
    constexpr int K = 128, BM = 64, BK = 32;
    constexpr int TX = BN / 4;       // 32 (BN=128) or 16 (BN=64)
    constexpr int TY = 256 / TX;     // 8 or 16
    constexpr int TM = BM / TY;      // 8 or 4
    __shared__ float As[BM][BK];
    __shared__ float Bs[BK][BN];
    int tid = threadIdx.x;
    int tx = tid % TX, ty = tid / TX;
    int row0 = blockIdx.x * BM;

    float acc[TM][4];
#pragma unroll
    for (int i = 0; i < TM; i++) { acc[i][0] = acc[i][1] = acc[i][2] = acc[i][3] = 0.f; }

    for (int kt = 0; kt < K; kt += BK) {
#pragma unroll
        for (int j = 0; j < (BM * BK) / 256; j++) {
            int idx = tid + j * 256;
            int r = idx >> 5;        // /BK (BK=32)
            int kk = idx & 31;
            int grow = row0 + r;
            As[r][kk] = (grow < M) ? A[(long long)grow * K + kt + kk] : 0.f;
        }
#pragma unroll
        for (int j = 0; j < (BK * BN) / 256; j++) {
            int idx = tid + j * 256;
            int kk = idx / BN;
            int nn = idx % BN;
            Bs[kk][nn] = B[(kt + kk) * BN + nn];
        }
        __syncthreads();
#pragma unroll
        for (int kk = 0; kk < BK; kk++) {
            float4 b4 = *(const float4*)&Bs[kk][tx * 4];
#pragma unroll
            for (int i = 0; i < TM; i++) {
                float a = As[ty + i * TY][kk];
                acc[i][0] = fmaf(a, b4.x, acc[i][0]);
                acc[i][1] = fmaf(a, b4.y, acc[i][1]);
                acc[i][2] = fmaf(a, b4.z, acc[i][2]);
                acc[i][3] = fmaf(a, b4.w, acc[i][3]);
            }
        }
        __syncthreads();
    }
#pragma unroll
    for (int i = 0; i < TM; i++) {
        int r = row0 + ty + i * TY;
        if (r < M) {
            float4 o = make_float4(acc[i][0], acc[i][1], acc[i][2], acc[i][3]);
            *(float4*)&C[(long long)r * BN + tx * 4] = o;
        }
    }
}

__global__ void k_gemm1(const float* __restrict__ x, const float* __restrict__ W1, int M) {
    gemm128<H1DIM>(x, W1, g_h1, M);
}
__global__ void k_gemm2(const float* __restrict__ W2, int M) {
    gemm128<OUTD>(g_out1, W2, g_h2, M);
}

// ---------------- attention coefficients (warp per node) ---------------------
template <int K, int H>
__device__ __forceinline__ void alpha_body(const float* __restrict__ h,
                                           const float* __restrict__ a_s,
                                           const float* __restrict__ a_d,
                                           float* __restrict__ als,
                                           float* __restrict__ ald, int n) {
    int w = (blockIdx.x * blockDim.x + threadIdx.x) >> 5;
    int lane = threadIdx.x & 31;
    if (w >= n) return;
    constexpr int L = K / 4;        // active lanes
    constexpr int GRP = L / H;      // lanes per head
    float ps = 0.f, pd = 0.f;
    if (lane < L) {
        float4 v  = *(const float4*)&h[(long long)w * K + lane * 4];
        float4 s4 = *(const float4*)&a_s[lane * 4];
        float4 d4 = *(const float4*)&a_d[lane * 4];
        ps = v.x * s4.x + v.y * s4.y + v.z * s4.z + v.w * s4.w;
        pd = v.x * d4.x + v.y * d4.y + v.z * d4.z + v.w * d4.w;
    }
#pragma unroll
    for (int o = GRP / 2; o > 0; o >>= 1) {
        ps += __shfl_down_sync(0xffffffffu, ps, o);
        pd += __shfl_down_sync(0xffffffffu, pd, o);
    }
    if (lane < L && (lane % GRP) == 0) {
        int head = lane / GRP;
        als[w * H + head] = ps;
        ald[w * H + head] = pd;
    }
}

__global__ void k_alpha1(const float* __restrict__ a_s, const float* __restrict__ a_d, int n) {
    alpha_body<H1DIM, NHEADS>(g_h1, a_s, a_d, g_als1, g_ald1, n);
}
__global__ void k_alpha2(const float* __restrict__ a_s, const float* __restrict__ a_d, int n) {
    alpha_body<OUTD, 1>(g_h2, a_s, a_d, g_als2, g_ald2, n);
}

__device__ __forceinline__ float lrelu(float e) { return e > 0.f ? e : SLOPE * e; }

// ---------------- layer 1 aggregation: warp per dst, lane = channel ----------
__global__ void k_agg1(const float* __restrict__ b1, int n) {
    int w = (blockIdx.x * blockDim.x + threadIdx.x) >> 5;
    int lane = threadIdx.x & 31;
    if (w >= n) return;

    float4 ad4 = *(const float4*)&g_ald1[w * 4];
    float adh[4] = {ad4.x, ad4.y, ad4.z, ad4.w};
    float4 as4 = *(const float4*)&g_als1[w * 4];
    float ash[4] = {as4.x, as4.y, as4.z, as4.w};

    float acc[4], z[4];
#pragma unroll
    for (int h = 0; h < 4; h++) {
        float wt = __expf(lrelu(ash[h] + adh[h]));   // self loop
        z[h] = wt;
        acc[h] = wt * g_h1[(long long)w * 128 + h * 32 + lane];
    }

    int p = g_off[w];
    int end = p + g_deg[w];
    int s = (p < end) ? g_csr[p] : 0;
    for (; p < end; p++) {
        int sc = s;
        if (p + 1 < end) s = g_csr[p + 1];           // prefetch next src id
        float4 a2 = *(const float4*)&g_als1[sc * 4];
        float a2h[4] = {a2.x, a2.y, a2.z, a2.w};
#pragma unroll
        for (int h = 0; h < 4; h++) {
            float wt = __expf(lrelu(a2h[h] + adh[h]));
            z[h] += wt;
            acc[h] = fmaf(wt, g_h1[(long long)sc * 128 + h * 32 + lane], acc[h]);
        }
    }
#pragma unroll
    for (int h = 0; h < 4; h++) {
        float v = acc[h] / (z[h] + 1e-16f) + b1[h * 32 + lane];
        g_out1[(long long)w * 128 + h * 32 + lane] = v > 0.f ? v : 0.f;
    }
}

// ---------------- layer 2 aggregation: warp per dst, lane covers c, c+32 -----
__global__ void k_agg2(const float* __restrict__ b2, float* __restrict__ out, int n) {
    int w = (blockIdx.x * blockDim.x + threadIdx.x) >> 5;
    int lane = threadIdx.x & 31;
    if (w >= n) return;

    float ad = g_ald2[w];
    float wt = __expf(lrelu(g_als2[w] + ad));        // self loop
    float z = wt;
    float acc0 = wt * g_h2[(long long)w * 64 + lane];
    float acc1 = wt * g_h2[(long long)w * 64 + 32 + lane];

    int p = g_off[w];
    int end = p + g_deg[w];
    int s = (p < end) ? g_csr[p] : 0;
    for (; p < end; p++) {
        int sc = s;
        if (p + 1 < end) s = g_csr[p + 1];
        float wt2 = __expf(lrelu(g_als2[sc] + ad));
        z += wt2;
        acc0 = fmaf(wt2, g_h2[(long long)sc * 64 + lane], acc0);
        acc1 = fmaf(wt2, g_h2[(long long)sc * 64 + 32 + lane], acc1);
    }
    float inv = 1.f / (z + 1e-16f);
    out[(long long)w * 64 + lane]      = acc0 * inv + b2[lane];
    out[(long long)w * 64 + 32 + lane] = acc1 * inv + b2[32 + lane];
}

// ---------------- launch -----------------------------------------------------
extern "C" void kernel_launch(void* const* d_in, const int* in_sizes, int n_in,
                              void* d_out, int out_size) {
    const float* x   = (const float*)d_in[0];
    const void*  ei  = d_in[1];                    // edge_index [2,E], int64 or int32
    const float* W1  = (const float*)d_in[3];
    const float* as1 = (const float*)d_in[4];
    const float* ad1 = (const float*)d_in[5];
    const float* b1  = (const float*)d_in[6];
    const float* W2  = (const float*)d_in[7];
    const float* as2 = (const float*)d_in[8];
    const float* ad2 = (const float*)d_in[9];
    const float* b2  = (const float*)d_in[10];
    float* out = (float*)d_out;

    int n = in_sizes[0] / IN_DIM;                  // 50000
    int e = in_sizes[1] / 2;                       // 800000
    int nb = (n + SCAN_CHUNK - 1) / SCAN_CHUNK;    // 49

    // edge dtype detection (probe odd 32-bit words)
    k_detect<<<1, 32>>>((const unsigned int*)ei);

    // CSR build over dst (multi-block 3-phase scan)
    k_zero<<<(n + 255) / 256, 256>>>(n);
    k_count<<<(e + 255) / 256, 256>>>(ei, e);
    k_scan_partial<<<nb, 256>>>(n);
    k_scan_part<<<1, MAX_PARTS>>>(nb);
    k_scan_final<<<nb, 256>>>(n);
    k_scatter<<<(e + 255) / 256, 256>>>(ei, e);

    // layer 1
    k_gemm1<<<(n + 63) / 64, 256>>>(x, W1, n);
    k_alpha1<<<(n * 32 + 255) / 256, 256>>>(as1, ad1, n);
    k_agg1<<<(n + 7) / 8, 256>>>(b1, n);

    // layer 2
    k_gemm2<<<(n + 63) / 64, 256>>>(W2, n);
    k_alpha2<<<(n * 32 + 255) / 256, 256>>>(as2, ad2, n);
    k_agg2<<<(n + 7) / 8, 256>>>(b2, out, n);
}